// round 3
// baseline (speedup 1.0000x reference)
#include <cuda_runtime.h>
#include <cuda_bf16.h>
#include <cstdint>
#include <math.h>

#define DIM   1024
#define TOK   4096
#define MA    32768
#define NU    34
#define FDIM  4096
#define SCL   0.03125f

__device__ float g_C [(size_t)DIM*DIM];
__device__ float g_CA[(size_t)MA*DIM];
__device__ float g_G [(size_t)MA*NU];
__device__ float g_U [(size_t)NU*DIM];
__device__ float g_CB[(size_t)TOK*32];
__device__ float g_Z [(size_t)TOK*DIM];
__device__ float g_CO[(size_t)TOK*DIM];
__device__ float g_H [(size_t)TOK*FDIM];
__device__ float g_pbv[32];
__device__ float g_c0[1];

#define BM 128
#define BN 128
#define BK 32
#define SROW 40
#define TILEH (BM*SROW)
#define GEMM_SMEM (2*4*TILEH*2)

__device__ __forceinline__ void mma_bf16(float c[4], const uint32_t a[4], const uint32_t b[2]){
  asm volatile(
    "mma.sync.aligned.m16n8k16.row.col.f32.bf16.bf16.f32 "
    "{%0,%1,%2,%3}, {%4,%5,%6,%7}, {%8,%9}, {%0,%1,%2,%3};\n"
    : "+f"(c[0]), "+f"(c[1]), "+f"(c[2]), "+f"(c[3])
    : "r"(a[0]), "r"(a[1]), "r"(a[2]), "r"(a[3]), "r"(b[0]), "r"(b[1]));
}

__device__ __forceinline__ void bsplit(float v, __nv_bfloat16 &h, __nv_bfloat16 &l){
  h = __float2bfloat16_rn(v);
  l = __float2bfloat16_rn(v - __bfloat162float(h));
}

// EPI: 0 store, 1 +bias, 2 gelu(+bias), 3 +bias+X2
template<int EPI>
__device__ __forceinline__ void emit_one(float* __restrict__ C, int row, int col, int N,
                                         float v, const float* __restrict__ bias,
                                         const float* __restrict__ X2){
  if (col >= N) return;
  if (EPI==1) v += bias[col];
  else if (EPI==2){ v += bias[col]; v = 0.5f*v*(1.0f + erff(v*0.70710678f)); }
  else if (EPI==3){ v += bias[col] + X2[(size_t)row*N + col]; }
  C[(size_t)row*N + col] = v;
}

// C[m,n] = sum_k A'[m,k]*B'[n,k];  TA: A'[m,k]=A[k*M+m]; TB: B'[n,k]=B[k*N+n]
// M %128==0, K %32==0, N arbitrary.
template<bool TA, bool TB, int EPI>
__global__ __launch_bounds__(256)
void gemm_k(const float* __restrict__ A, const float* __restrict__ B,
            float* __restrict__ C, int M, int N, int K,
            const float* __restrict__ bias, const float* __restrict__ X2)
{
  extern __shared__ char dynsm[];
  __nv_bfloat16* sbase = (__nv_bfloat16*)dynsm;
  const int tid = threadIdx.x;
  const int mBase = blockIdx.y * BM;
  const int nBase = blockIdx.x * BN;

  float acc[2][8][4];
#pragma unroll
  for (int a=0;a<2;a++)
#pragma unroll
    for (int b=0;b<8;b++)
#pragma unroll
      for (int c=0;c<4;c++) acc[a][b][c]=0.f;

  float4 pa[4], pb[4];
  const int nK = K / BK;

  auto loadA = [&](int k0){
    if (!TA){
#pragma unroll
      for (int it=0; it<4; ++it){
        int id = tid + it*256, row = id>>3, c4 = id&7;
        pa[it] = *(const float4*)(A + (size_t)(mBase+row)*K + k0 + c4*4);
      }
    } else {
#pragma unroll
      for (int it=0; it<4; ++it){
        int kk = (tid>>5) + it*8, m4 = tid&31;
        pa[it] = *(const float4*)(A + (size_t)(k0+kk)*M + mBase + m4*4);
      }
    }
  };
  auto loadB = [&](int k0){
    if (!TB){
#pragma unroll
      for (int it=0; it<4; ++it){
        int id = tid + it*256, row = id>>3, c4 = id&7;
        if (nBase + row < N)
          pb[it] = *(const float4*)(B + (size_t)(nBase+row)*K + k0 + c4*4);
        else pb[it] = make_float4(0.f,0.f,0.f,0.f);
      }
    } else {
#pragma unroll
      for (int it=0; it<4; ++it){
        int kk = (tid>>5) + it*8, n4 = tid&31;
        int n0 = nBase + n4*4;
        if (n0 + 3 < N){
          pb[it] = *(const float4*)(B + (size_t)(k0+kk)*N + n0);
        } else {
          float t0 = (n0   < N) ? B[(size_t)(k0+kk)*N + n0  ] : 0.f;
          float t1 = (n0+1 < N) ? B[(size_t)(k0+kk)*N + n0+1] : 0.f;
          float t2 = (n0+2 < N) ? B[(size_t)(k0+kk)*N + n0+2] : 0.f;
          float t3 = (n0+3 < N) ? B[(size_t)(k0+kk)*N + n0+3] : 0.f;
          pb[it] = make_float4(t0,t1,t2,t3);
        }
      }
    }
  };

  auto stsAll = [&](int stage){
    __nv_bfloat16* hA = sbase + stage*4*TILEH;
    __nv_bfloat16* lA = hA + TILEH;
    __nv_bfloat16* hB = lA + TILEH;
    __nv_bfloat16* lB = hB + TILEH;
#pragma unroll
    for (int it=0; it<4; ++it){
      float v[4] = {pa[it].x, pa[it].y, pa[it].z, pa[it].w};
      if (!TA){
        int id = tid + it*256, row = id>>3, c4 = id&7;
#pragma unroll
        for (int u=0;u<4;u++){ __nv_bfloat16 h,l; bsplit(v[u],h,l);
          hA[row*SROW + c4*4 + u] = h; lA[row*SROW + c4*4 + u] = l; }
      } else {
        int kk = (tid>>5) + it*8, m4 = tid&31;
#pragma unroll
        for (int u=0;u<4;u++){ __nv_bfloat16 h,l; bsplit(v[u],h,l);
          hA[(m4*4+u)*SROW + kk] = h; lA[(m4*4+u)*SROW + kk] = l; }
      }
    }
#pragma unroll
    for (int it=0; it<4; ++it){
      float v[4] = {pb[it].x, pb[it].y, pb[it].z, pb[it].w};
      if (!TB){
        int id = tid + it*256, row = id>>3, c4 = id&7;
#pragma unroll
        for (int u=0;u<4;u++){ __nv_bfloat16 h,l; bsplit(v[u],h,l);
          hB[row*SROW + c4*4 + u] = h; lB[row*SROW + c4*4 + u] = l; }
      } else {
        int kk = (tid>>5) + it*8, n4 = tid&31;
#pragma unroll
        for (int u=0;u<4;u++){ __nv_bfloat16 h,l; bsplit(v[u],h,l);
          hB[(n4*4+u)*SROW + kk] = h; lB[(n4*4+u)*SROW + kk] = l; }
      }
    }
  };

  loadA(0); loadB(0); stsAll(0);
  __syncthreads();

  const int warp = tid>>5, lane = tid&31;
  const int wm = (warp>>1)*32, wn = (warp&1)*64;
  const int r = lane>>2, c2 = (lane&3)*2;

  for (int kt=0; kt<nK; ++kt){
    int nxt = kt+1;
    if (nxt < nK){ loadA(nxt*BK); loadB(nxt*BK); }
    {
      const __nv_bfloat16* hA = sbase + (kt&1)*4*TILEH;
      const __nv_bfloat16* lA = hA + TILEH;
      const __nv_bfloat16* hB = lA + TILEH;
      const __nv_bfloat16* lB = hB + TILEH;
#pragma unroll
      for (int s=0;s<2;s++){
        uint32_t ah[2][4], al[2][4];
        int cc = c2 + s*16;
#pragma unroll
        for (int mt=0;mt<2;mt++){
          int rr = wm + mt*16 + r;
          ah[mt][0] = *(const uint32_t*)(hA + rr*SROW + cc);
          ah[mt][1] = *(const uint32_t*)(hA + (rr+8)*SROW + cc);
          ah[mt][2] = *(const uint32_t*)(hA + rr*SROW + cc + 8);
          ah[mt][3] = *(const uint32_t*)(hA + (rr+8)*SROW + cc + 8);
          al[mt][0] = *(const uint32_t*)(lA + rr*SROW + cc);
          al[mt][1] = *(const uint32_t*)(lA + (rr+8)*SROW + cc);
          al[mt][2] = *(const uint32_t*)(lA + rr*SROW + cc + 8);
          al[mt][3] = *(const uint32_t*)(lA + (rr+8)*SROW + cc + 8);
        }
#pragma unroll
        for (int nt=0;nt<8;nt++){
          int bn = wn + nt*8 + r;
          uint32_t bh[2], bl[2];
          bh[0] = *(const uint32_t*)(hB + bn*SROW + cc);
          bh[1] = *(const uint32_t*)(hB + bn*SROW + cc + 8);
          bl[0] = *(const uint32_t*)(lB + bn*SROW + cc);
          bl[1] = *(const uint32_t*)(lB + bn*SROW + cc + 8);
#pragma unroll
          for (int mt=0;mt<2;mt++){
            mma_bf16(acc[mt][nt], ah[mt], bh);
            mma_bf16(acc[mt][nt], ah[mt], bl);
            mma_bf16(acc[mt][nt], al[mt], bh);
          }
        }
      }
    }
    if (nxt < nK) stsAll(nxt&1);
    __syncthreads();
  }

#pragma unroll
  for (int mt=0;mt<2;mt++){
#pragma unroll
    for (int nt=0;nt<8;nt++){
      int row = mBase + wm + mt*16 + r;
      int col = nBase + wn + nt*8 + c2;
      emit_one<EPI>(C, row,   col,   N, acc[mt][nt][0], bias, X2);
      emit_one<EPI>(C, row,   col+1, N, acc[mt][nt][1], bias, X2);
      emit_one<EPI>(C, row+8, col,   N, acc[mt][nt][2], bias, X2);
      emit_one<EPI>(C, row+8, col+1, N, acc[mt][nt][3], bias, X2);
    }
  }
}

// U' rows 0..31 = Pq@Wv ; 32: u1[d]=sum_e bq[e]Wk[e,d] ; 33: u2[d]=sum_e Wq[e,d]bk[e]
__global__ __launch_bounds__(256)
void prep_k(const float* __restrict__ Pq, const float* __restrict__ Wv,
            const float* __restrict__ Wk, const float* __restrict__ Wq,
            const float* __restrict__ bq, const float* __restrict__ bk,
            const float* __restrict__ bv,
            float* __restrict__ U, float* __restrict__ pbv, float* __restrict__ c0)
{
  __shared__ float srow[DIM];
  int b = blockIdx.x, tid = threadIdx.x;
  if (b < 32){
    for (int e=tid;e<DIM;e+=256) srow[e]=Pq[b*DIM+e];
    __syncthreads();
    for (int d=tid; d<DIM; d+=256){
      float acc=0.f;
      for (int e=0;e<DIM;e++) acc += srow[e]*Wv[(size_t)e*DIM+d];
      U[(size_t)b*DIM+d]=acc;
    }
  } else if (b==32){
    for (int e=tid;e<DIM;e+=256) srow[e]=bq[e];
    __syncthreads();
    for (int d=tid; d<DIM; d+=256){
      float acc=0.f;
      for (int e=0;e<DIM;e++) acc += srow[e]*Wk[(size_t)e*DIM+d];
      U[(size_t)32*DIM+d]=acc;
    }
  } else if (b==33){
    for (int e=tid;e<DIM;e+=256) srow[e]=bk[e];
    __syncthreads();
    for (int d=tid; d<DIM; d+=256){
      float acc=0.f;
      for (int e=0;e<DIM;e++) acc += srow[e]*Wq[(size_t)e*DIM+d];
      U[(size_t)33*DIM+d]=acc;
    }
  } else if (b==34){
    int w = tid>>5, l = tid&31;
    for (int p=w; p<32; p+=8){
      float acc=0.f;
      for (int d=l; d<DIM; d+=32) acc += Pq[p*DIM+d]*bv[d];
      for (int o=16;o;o>>=1) acc += __shfl_down_sync(0xffffffffu, acc, o);
      if (l==0) pbv[p]=acc;
    }
  } else {
    __shared__ float red[256];
    float acc=0.f;
    for (int d=tid; d<DIM; d+=256) acc += bq[d]*bk[d];
    red[tid]=acc; __syncthreads();
    for (int s=128; s>0; s>>=1){ if (tid<s) red[tid]+=red[tid+s]; __syncthreads(); }
    if (tid==0) c0[0]=red[0];
  }
}

__global__ __launch_bounds__(256)
void token_k(const float* __restrict__ A, const float* __restrict__ CA,
             const float* __restrict__ GA, const float* __restrict__ CB,
             const float* __restrict__ tkw, const float* __restrict__ pbv,
             const float* __restrict__ c0p, float* __restrict__ Z)
{
  extern __shared__ float sm[];
  float* sA = sm;         // 8*1024
  float* sC = sm + 8192;  // 8*1024
  __shared__ float sGA[8][NU];
  __shared__ float sS[64];
  __shared__ float sAttn[64];
  __shared__ float sNps[32][8];
  __shared__ float sFa[8];
  __shared__ float sW[8];
  __shared__ float sScore[32];

  const int t = blockIdx.x, tid = threadIdx.x;
  const size_t base = (size_t)t*8*DIM;
  const float4* A4 = (const float4*)(A + base);
  const float4* C4 = (const float4*)(CA + base);
  float4* sA4 = (float4*)sA; float4* sC4 = (float4*)sC;
  for (int i=tid; i<2048; i+=256){ sA4[i]=A4[i]; sC4[i]=C4[i]; }
  for (int i=tid; i<8*NU; i+=256) sGA[i/NU][i%NU] = GA[(size_t)(t*8 + i/NU)*NU + i%NU];
  __syncthreads();

  int warp = tid>>5, lane = tid&31;
  for (int p8=0;p8<8;p8++){
    int pair = warp*8+p8;
    const float* ai = sA + (pair>>3)*DIM;
    const float* cj = sC + (pair&7)*DIM;
    float acc=0.f;
    for (int d=lane; d<DIM; d+=32) acc += ai[d]*cj[d];
    for (int o=16;o;o>>=1) acc += __shfl_xor_sync(0xffffffffu, acc, o);
    if (lane==0) sS[pair]=acc;
  }
  __syncthreads();

  float c0 = c0p[0];
  if (warp==0 && lane<8){
    int i=lane;
    float s[8], mx=-1e30f;
    for (int j=0;j<8;j++){ s[j]=SCL*(sS[i*8+j]+sGA[j][32]+sGA[i][33]+c0); mx=fmaxf(mx,s[j]); }
    float sum=0.f;
    for (int j=0;j<8;j++){ s[j]=expf(s[j]-mx); sum+=s[j]; }
    float inv=1.f/sum;
    for (int j=0;j<8;j++) sAttn[i*8+j]=s[j]*inv;
  }
  __syncthreads();
  if (warp==1){
    int p=lane;
    const float* w8 = tkw + (size_t)t*8;
    float nb=0.f;
    for (int i=0;i<8;i++){
      float acc=0.f;
      for (int j=0;j<8;j++) acc += sAttn[i*8+j]*sGA[j][p];
      float nps = SCL*(acc + pbv[p]);
      sNps[p][i]=nps;
      nb += nps * w8[i];
    }
    sScore[p] = 0.5f*nb + 0.5f*CB[(size_t)t*32+p];
  }
  __syncthreads();
  if (tid==0){
    int sel[4]; float sv[4];
    unsigned used=0u;
    for (int r2=0;r2<4;r2++){
      float best=-1e30f; int bi=0;
      for (int p=0;p<32;p++) if(!((used>>p)&1u) && sScore[p]>best){best=sScore[p];bi=p;}
      used |= 1u<<bi; sel[r2]=bi; sv[r2]=best;
    }
    float mx=sv[0], tw[4], sum=0.f;
    for(int r2=0;r2<4;r2++){ tw[r2]=expf(sv[r2]-mx); sum+=tw[r2]; }
    float fa[8]={0,0,0,0,0,0,0,0};
    for(int r2=0;r2<4;r2++){
      int p=sel[r2];
      float m2=-1e30f;
      for(int k=0;k<8;k++) m2=fmaxf(m2,sNps[p][k]);
      float e[8], s2=0.f;
      for(int k=0;k<8;k++){ e[k]=expf(sNps[p][k]-m2); s2+=e[k]; }
      float inv=(tw[r2]/sum)/s2;
      for(int k=0;k<8;k++) fa[k]+=e[k]*inv;
    }
    for(int k=0;k<8;k++) sFa[k]=fa[k];
  }
  __syncthreads();
  if (tid<8){
    float w=0.f;
    for(int i=0;i<8;i++) w += sFa[i]*sAttn[i*8+tid];
    sW[tid]=w;
  }
  __syncthreads();
  for (int d=tid; d<DIM; d+=256){
    float acc=0.f;
    for(int j=0;j<8;j++) acc += sW[j]*sA[j*DIM+d];
    Z[(size_t)t*DIM+d]=acc;
  }
}

extern "C" void kernel_launch(void* const* d_in, const int* in_sizes, int n_in,
                              void* d_out, int out_size) {
  const float* x    = (const float*)d_in[0];
  const float* tkw  = (const float*)d_in[3];
  const float* A    = (const float*)d_in[4];
  const float* ctx  = (const float*)d_in[5];
  const float* Wq   = (const float*)d_in[6];
  const float* bq   = (const float*)d_in[7];
  const float* Wk   = (const float*)d_in[8];
  const float* bk   = (const float*)d_in[9];
  const float* Wv   = (const float*)d_in[10];
  const float* bv   = (const float*)d_in[11];
  const float* Pq   = (const float*)d_in[12];
  const float* Wup  = (const float*)d_in[13];
  const float* bup  = (const float*)d_in[14];
  const float* Wdn  = (const float*)d_in[15];
  const float* bdn  = (const float*)d_in[16];
  float* out = (float*)d_out;

  float *pC, *pCA, *pG, *pU, *pCB, *pZ, *pCO, *pH, *ppbv, *pc0;
  cudaGetSymbolAddress((void**)&pC,  g_C);
  cudaGetSymbolAddress((void**)&pCA, g_CA);
  cudaGetSymbolAddress((void**)&pG,  g_G);
  cudaGetSymbolAddress((void**)&pU,  g_U);
  cudaGetSymbolAddress((void**)&pCB, g_CB);
  cudaGetSymbolAddress((void**)&pZ,  g_Z);
  cudaGetSymbolAddress((void**)&pCO, g_CO);
  cudaGetSymbolAddress((void**)&pH,  g_H);
  cudaGetSymbolAddress((void**)&ppbv,g_pbv);
  cudaGetSymbolAddress((void**)&pc0, g_c0);

  cudaFuncSetAttribute(gemm_k<true ,true ,0>, cudaFuncAttributeMaxDynamicSharedMemorySize, GEMM_SMEM);
  cudaFuncSetAttribute(gemm_k<false,false,0>, cudaFuncAttributeMaxDynamicSharedMemorySize, GEMM_SMEM);
  cudaFuncSetAttribute(gemm_k<false,false,1>, cudaFuncAttributeMaxDynamicSharedMemorySize, GEMM_SMEM);
  cudaFuncSetAttribute(gemm_k<false,false,2>, cudaFuncAttributeMaxDynamicSharedMemorySize, GEMM_SMEM);
  cudaFuncSetAttribute(gemm_k<false,false,3>, cudaFuncAttributeMaxDynamicSharedMemorySize, GEMM_SMEM);
  cudaFuncSetAttribute(token_k, cudaFuncAttributeMaxDynamicSharedMemorySize, 65536);

  prep_k<<<36,256>>>(Pq, Wv, Wk, Wq, bq, bk, bv, pU, ppbv, pc0);
  // C = Wq^T Wk
  gemm_k<true,true,0><<<dim3(8,8),256,GEMM_SMEM>>>(Wq, Wk, pC, DIM, DIM, DIM, nullptr, nullptr);
  // CA = A @ C^T
  gemm_k<false,false,0><<<dim3(8,256),256,GEMM_SMEM>>>(A, pC, pCA, MA, DIM, DIM, nullptr, nullptr);
  // G = A @ U'^T
  gemm_k<false,false,0><<<dim3(1,256),256,GEMM_SMEM>>>(A, pU, pG, MA, NU, DIM, nullptr, nullptr);
  // CB = context @ Pq^T
  gemm_k<false,false,0><<<dim3(1,32),256,GEMM_SMEM>>>(ctx, Pq, pCB, TOK, 32, DIM, nullptr, nullptr);
  // per-token attention -> Z
  token_k<<<TOK,256,65536>>>(A, pCA, pG, pCB, tkw, ppbv, pc0, pZ);
  // combined = Z @ Wv^T + bv + x
  gemm_k<false,false,3><<<dim3(8,32),256,GEMM_SMEM>>>(pZ, Wv, pCO, TOK, DIM, DIM, bv, x);
  // H = gelu(combined @ Wup^T + bup)
  gemm_k<false,false,2><<<dim3(32,32),256,GEMM_SMEM>>>(pCO, Wup, pH, TOK, FDIM, DIM, bup, nullptr);
  // out = H @ Wdown^T + bdown
  gemm_k<false,false,1><<<dim3(8,32),256,GEMM_SMEM>>>(pH, Wdn, out, TOK, DIM, FDIM, bdn, nullptr);
}

// round 6
// speedup vs baseline: 1.0303x; 1.0303x over previous
#include <cuda_runtime.h>
#include <cuda_bf16.h>
#include <cstdint>
#include <math.h>
#define DIM 1024
#define TOK 4096
#define MA 32768
#define NU 34
#define FDIM 4096
#define SCL 0.03125f
typedef __nv_bfloat16 bf16;

__device__ float g_CA[(size_t)MA*DIM];
__device__ float g_G [(size_t)MA*NU];
__device__ float g_CB[(size_t)TOK*32];
__device__ float g_Z [(size_t)TOK*DIM];
__device__ float g_U [(size_t)NU*DIM];
__device__ float g_pbv[32], g_c0[1];
__device__ __align__(256) bf16 e_A [(size_t)MA*3*DIM];
__device__ __align__(256) bf16 e_Wq[(size_t)DIM*3*DIM];
__device__ __align__(256) bf16 e_Wk[(size_t)DIM*3*DIM];
__device__ __align__(256) bf16 e_C [(size_t)DIM*3*DIM];
__device__ __align__(256) bf16 e_U [(size_t)NU*3*DIM];
__device__ __align__(256) bf16 e_cx[(size_t)TOK*3*DIM];
__device__ __align__(256) bf16 e_Pq[(size_t)32*3*DIM];
__device__ __align__(256) bf16 e_Z [(size_t)TOK*3*DIM];
__device__ __align__(256) bf16 e_Wv[(size_t)DIM*3*DIM];
__device__ __align__(256) bf16 e_CO[(size_t)TOK*3*DIM];
__device__ __align__(256) bf16 e_Wu[(size_t)FDIM*3*DIM];
__device__ __align__(256) bf16 e_H [(size_t)TOK*3*FDIM];
__device__ __align__(256) bf16 e_Wd[(size_t)DIM*3*FDIM];

__device__ __forceinline__ uint32_t smem_u32(const void* p){
  uint32_t a;
  asm("{ .reg .u64 t; cvta.to.shared.u64 t, %1; cvt.u32.u64 %0, t; }" : "=r"(a) : "l"(p));
  return a;
}
__device__ __forceinline__ void cpa16(uint32_t s, const void* g){
  asm volatile("cp.async.cg.shared.global [%0], [%1], 16;\n" :: "r"(s), "l"(g));
}
__device__ __forceinline__ void mma_bf16(float c[4], const uint32_t a[4], const uint32_t b[2]){
  asm volatile(
    "mma.sync.aligned.m16n8k16.row.col.f32.bf16.bf16.f32 "
    "{%0,%1,%2,%3}, {%4,%5,%6,%7}, {%8,%9}, {%0,%1,%2,%3};\n"
    : "+f"(c[0]), "+f"(c[1]), "+f"(c[2]), "+f"(c[3])
    : "r"(a[0]), "r"(a[1]), "r"(a[2]), "r"(a[3]), "r"(b[0]), "r"(b[1]));
}
__device__ __forceinline__ void bsp(float v, bf16 &h, bf16 &l){
  h = __float2bfloat16_rn(v); l = __float2bfloat16_rn(v - __bfloat162float(h));
}

// EPI: 0 fp32 | 1 Bext(h,h,l) | 3 +bias+X2->Aext | 4 gelu(+bias)->Aext | 5 +bias->fp32
template<int EPI>
__device__ __forceinline__ void emit(float v, int m, int col, int N,
                                     float* Cf, bf16* Ce,
                                     const float* bias, const float* X2){
  if (EPI==3) v += bias[col] + X2[(size_t)m*N + col];
  if (EPI==4){ v += bias[col]; v = 0.5f*v*(1.0f + erff(v*0.70710678f)); }
  if (EPI==5){ Cf[(size_t)m*N + col] = v + bias[col]; return; }
  if (EPI==0){ Cf[(size_t)m*N + col] = v; return; }
  bf16 h, l; bsp(v, h, l);
  size_t b = (size_t)m*3*N;
  Ce[b + col] = h;
  Ce[b + N + col]   = (EPI==1) ? h : l;
  Ce[b + 2*N + col] = (EPI==1) ? l : h;
}

// C[m,n] = sum_k A[m,k]*B[n,k]; bf16 K-major ext operands. M%128==0, K%64==0.
// BK=64, SROW=72 halfs (144B rows: conflict-free LDS, 16B-aligned cp.async).
template<int BN, int EPI>
__global__ __launch_bounds__(256,2)
void lg_k(const bf16* __restrict__ A, const bf16* __restrict__ B,
          int K, int N, int Nb,
          float* __restrict__ Cf, bf16* __restrict__ Ce,
          const float* __restrict__ bias, const float* __restrict__ X2)
{
  constexpr int SROW = 72;
  constexpr int ATILE = 128*SROW;               // halfs
  constexpr int STAGE = (128+BN)*SROW;          // halfs
  constexpr int NCH = (128+BN)*8;               // 16B chunks per stage
  constexpr int CHT = NCH/256;
  constexpr int WN = BN/2;                      // warp n-extent
  extern __shared__ __align__(16) char smraw[];
  bf16* sb = (bf16*)smraw;
  const int tid = threadIdx.x;
  const int mBase = blockIdx.y*128, nBase = blockIdx.x*BN;
  const uint32_t smu = smem_u32(sb);

  uint32_t soff[CHT]; const bf16* gp[CHT]; bool val[CHT];
#pragma unroll
  for (int i=0;i<CHT;i++){
    const int c = tid + i*256;
    const int row = c>>3, kc = c&7;
    const bool isA = row < 128;
    const int lrow = isA ? row : row-128;
    const int sh = (isA ? 0 : ATILE) + lrow*SROW + kc*8;
    soff[i] = smu + sh*2;
    const int gr = isA ? (mBase+row) : (nBase+lrow);
    gp[i] = (isA ? A : B) + (size_t)gr*K + kc*8;
    val[i] = isA || (nBase+lrow) < Nb;
    if (!val[i]){
      uint4 z = {0u,0u,0u,0u};
      *(uint4*)(sb + sh) = z;
      *(uint4*)(sb + sh + STAGE) = z;
    }
  }
  auto loadStage = [&](int s){
    const uint32_t add = s ? (uint32_t)(STAGE*2) : 0u;
#pragma unroll
    for (int i=0;i<CHT;i++){
      if (val[i]) cpa16(soff[i]+add, gp[i]);
      gp[i] += 64;
    }
    asm volatile("cp.async.commit_group;\n":::"memory");
  };

  float acc[2][WN/8][4];
#pragma unroll
  for (int a=0;a<2;a++)
#pragma unroll
    for (int b=0;b<WN/8;b++)
#pragma unroll
      for (int c=0;c<4;c++) acc[a][b][c]=0.f;

  const int warp = tid>>5, lane = tid&31;
  const int wm = (warp>>1)*32, wn = (warp&1)*WN;
  const int r = lane>>2, c2 = (lane&3)*2;

  loadStage(0);
  const int nK = K/64;
  for (int kt=0; kt<nK; ++kt){
    const int s = kt & 1;
    if (kt+1 < nK){
      loadStage(s^1);
      asm volatile("cp.async.wait_group 1;\n":::"memory");
    } else {
      asm volatile("cp.async.wait_group 0;\n":::"memory");
    }
    __syncthreads();
    const bf16* hA = sb + s*STAGE;
    const bf16* hB = hA + ATILE;
#pragma unroll
    for (int ks=0; ks<4; ++ks){
      const int cc = c2 + ks*16;
      uint32_t ah[2][4];
#pragma unroll
      for (int mt=0;mt<2;mt++){
        const int rr = wm + mt*16 + r;
        ah[mt][0] = *(const uint32_t*)(hA + rr*SROW + cc);
        ah[mt][1] = *(const uint32_t*)(hA + (rr+8)*SROW + cc);
        ah[mt][2] = *(const uint32_t*)(hA + rr*SROW + cc + 8);
        ah[mt][3] = *(const uint32_t*)(hA + (rr+8)*SROW + cc + 8);
      }
#pragma unroll
      for (int nt=0; nt<WN/8; nt++){
        const int bn = wn + nt*8 + r;
        uint32_t bh[2];
        bh[0] = *(const uint32_t*)(hB + bn*SROW + cc);
        bh[1] = *(const uint32_t*)(hB + bn*SROW + cc + 8);
#pragma unroll
        for (int mt=0;mt<2;mt++) mma_bf16(acc[mt][nt], ah[mt], bh);
      }
    }
    __syncthreads();
  }

#pragma unroll
  for (int mt=0;mt<2;mt++){
#pragma unroll
    for (int nt=0; nt<WN/8; nt++){
      const int row = mBase + wm + mt*16 + r;
      const int col = nBase + wn + nt*8 + c2;
      if (col < N){
        emit<EPI>(acc[mt][nt][0], row, col, N, Cf, Ce, bias, X2);
        emit<EPI>(acc[mt][nt][2], row+8, col, N, Cf, Ce, bias, X2);
      }
      if (col+1 < N){
        emit<EPI>(acc[mt][nt][1], row, col+1, N, Cf, Ce, bias, X2);
        emit<EPI>(acc[mt][nt][3], row+8, col+1, N, Cf, Ce, bias, X2);
      }
    }
  }
}

// fp32 [R,C] -> ext (A-side h,l,h / B-side h,h,l), row stride 3C
template<bool ASIDE>
__global__ __launch_bounds__(256)
void conv_k(const float* __restrict__ S, bf16* __restrict__ E, int C, long n4){
  long i = (long)blockIdx.x*256 + threadIdx.x;
  if (i >= n4) return;
  int c4 = C/4;
  int r = (int)(i / c4), cc = (int)(i % c4) * 4;
  float4 v = ((const float4*)S)[i];
  float vv[4] = {v.x, v.y, v.z, v.w};
  bf16 h[4], l[4];
#pragma unroll
  for (int u=0;u<4;u++) bsp(vv[u], h[u], l[u]);
  uint2 ph = *(uint2*)h, pl = *(uint2*)l;
  size_t b = (size_t)r*3*C + cc;
  *(uint2*)(E + b)       = ph;
  *(uint2*)(E + b + C)   = ASIDE ? pl : ph;
  *(uint2*)(E + b + 2*C) = ASIDE ? ph : pl;
}
// ext of S^T for S [DIM,DIM]
template<bool ASIDE>
__global__ __launch_bounds__(256)
void convT_k(const float* __restrict__ S, bf16* __restrict__ E){
  __shared__ float t[32][33];
  const int bx = blockIdx.x*32, by = blockIdx.y*32;
  const int tx = threadIdx.x&31, ty = threadIdx.x>>5;
  for (int r=0;r<32;r+=8) t[ty+r][tx] = S[(size_t)(by+ty+r)*DIM + bx+tx];
  __syncthreads();
  for (int r=0;r<32;r+=8){
    float v = t[ty+r][tx];
    bf16 h, l; bsp(v, h, l);
    size_t b = (size_t)(bx+tx)*3*DIM + (by+ty+r);
    E[b] = h;
    E[b + DIM]   = ASIDE ? l : h;
    E[b + 2*DIM] = ASIDE ? h : l;
  }
}

__global__ __launch_bounds__(256)
void prep_k(const float* __restrict__ Pq, const float* __restrict__ Wv,
            const float* __restrict__ Wk, const float* __restrict__ Wq,
            const float* __restrict__ bq, const float* __restrict__ bk,
            const float* __restrict__ bv,
            float* __restrict__ U, float* __restrict__ pbv, float* __restrict__ c0)
{
  __shared__ float srow[DIM];
  int b = blockIdx.x, tid = threadIdx.x;
  if (b < 34){
    const float* src = (b<32) ? Pq + b*DIM : ((b==32) ? bq : bk);
    const float* W   = (b<32) ? Wv : ((b==32) ? Wk : Wq);
    for (int e=tid;e<DIM;e+=256) srow[e]=src[e];
    __syncthreads();
    for (int d=tid; d<DIM; d+=256){
      float acc=0.f;
      for (int e=0;e<DIM;e++) acc += srow[e]*W[(size_t)e*DIM+d];
      U[(size_t)b*DIM+d]=acc;
    }
  } else if (b==34){
    int w = tid>>5, l = tid&31;
    for (int p=w; p<32; p+=8){
      float acc=0.f;
      for (int d=l; d<DIM; d+=32) acc += Pq[p*DIM+d]*bv[d];
      for (int o=16;o;o>>=1) acc += __shfl_down_sync(0xffffffffu, acc, o);
      if (l==0) pbv[p]=acc;
    }
  } else {
    __shared__ float red[256];
    float acc=0.f;
    for (int d=tid; d<DIM; d+=256) acc += bq[d]*bk[d];
    red[tid]=acc; __syncthreads();
    for (int s=128; s>0; s>>=1){ if (tid<s) red[tid]+=red[tid+s]; __syncthreads(); }
    if (tid==0) c0[0]=red[0];
  }
}

__global__ __launch_bounds__(256)
void token_k(const float* __restrict__ A, const float* __restrict__ CA,
             const float* __restrict__ GA, const float* __restrict__ CB,
             const float* __restrict__ tkw, const float* __restrict__ pbv,
             const float* __restrict__ c0p, float* __restrict__ Z)
{
  extern __shared__ __align__(16) char smraw[];
  float* sA = (float*)smraw; float* sC = sA + 8192;
  __shared__ float sGA[8][NU];
  __shared__ float sS[64], sAttn[64], sNps[32][8], sFa[8], sW[8], sScore[32];
  const int t = blockIdx.x, tid = threadIdx.x;
  const size_t base = (size_t)t*8*DIM;
  const float4* A4 = (const float4*)(A + base);
  const float4* C4 = (const float4*)(CA + base);
  float4* sA4 = (float4*)sA; float4* sC4 = (float4*)sC;
  for (int i=tid; i<2048; i+=256){ sA4[i]=A4[i]; sC4[i]=C4[i]; }
  for (int i=tid; i<8*NU; i+=256) sGA[i/NU][i%NU] = GA[(size_t)(t*8 + i/NU)*NU + i%NU];
  __syncthreads();
  int warp = tid>>5, lane = tid&31;
  for (int p8=0;p8<8;p8++){
    int pair = warp*8+p8;
    const float* ai = sA + (pair>>3)*DIM;
    const float* cj = sC + (pair&7)*DIM;
    float acc=0.f;
    for (int d=lane; d<DIM; d+=32) acc += ai[d]*cj[d];
    for (int o=16;o;o>>=1) acc += __shfl_xor_sync(0xffffffffu, acc, o);
    if (lane==0) sS[pair]=acc;
  }
  __syncthreads();
  float c0 = c0p[0];
  if (warp==0 && lane<8){
    int i=lane;
    float s[8], mx=-1e30f;
    for (int j=0;j<8;j++){ s[j]=SCL*(sS[i*8+j]+sGA[j][32]+sGA[i][33]+c0); mx=fmaxf(mx,s[j]); }
    float sum=0.f;
    for (int j=0;j<8;j++){ s[j]=expf(s[j]-mx); sum+=s[j]; }
    float inv=1.f/sum;
    for (int j=0;j<8;j++) sAttn[i*8+j]=s[j]*inv;
  }
  __syncthreads();
  if (warp==1){
    int p=lane;
    const float* w8 = tkw + (size_t)t*8;
    float nb=0.f;
    for (int i=0;i<8;i++){
      float acc=0.f;
      for (int j=0;j<8;j++) acc += sAttn[i*8+j]*sGA[j][p];
      float nps = SCL*(acc + pbv[p]);
      sNps[p][i]=nps; nb += nps * w8[i];
    }
    sScore[p] = 0.5f*nb + 0.5f*CB[(size_t)t*32+p];
  }
  __syncthreads();
  if (tid==0){
    int sel[4]; float sv[4]; unsigned used=0u;
    for (int r2=0;r2<4;r2++){
      float best=-1e30f; int bi=0;
      for (int p=0;p<32;p++) if(!((used>>p)&1u) && sScore[p]>best){best=sScore[p];bi=p;}
      used |= 1u<<bi; sel[r2]=bi; sv[r2]=best;
    }
    float mx=sv[0], tw[4], sum=0.f;
    for(int r2=0;r2<4;r2++){ tw[r2]=expf(sv[r2]-mx); sum+=tw[r2]; }
    float fa[8]={0,0,0,0,0,0,0,0};
    for(int r2=0;r2<4;r2++){
      int p=sel[r2];
      float m2=-1e30f;
      for(int k=0;k<8;k++) m2=fmaxf(m2,sNps[p][k]);
      float e[8], s2=0.f;
      for(int k=0;k<8;k++){ e[k]=expf(sNps[p][k]-m2); s2+=e[k]; }
      float inv=(tw[r2]/sum)/s2;
      for(int k=0;k<8;k++) fa[k]+=e[k]*inv;
    }
    for(int k=0;k<8;k++) sFa[k]=fa[k];
  }
  __syncthreads();
  if (tid<8){
    float w=0.f;
    for(int i=0;i<8;i++) w += sFa[i]*sAttn[i*8+tid];
    sW[tid]=w;
  }
  __syncthreads();
  for (int d=tid; d<DIM; d+=256){
    float acc=0.f;
    for(int j=0;j<8;j++) acc += sW[j]*sA[j*DIM+d];
    Z[(size_t)t*DIM+d]=acc;
  }
}

#define SM128B (2*(128+128)*72*2)
#define SM64B  (2*(128+64)*72*2)
extern "C" void kernel_launch(void* const* d_in, const int* in_sizes, int n_in,
                              void* d_out, int out_size) {
  const float* x   = (const float*)d_in[0];
  const float* tkw = (const float*)d_in[3];
  const float* A   = (const float*)d_in[4];
  const float* ctx = (const float*)d_in[5];
  const float* Wq  = (const float*)d_in[6];
  const float* bq  = (const float*)d_in[7];
  const float* Wk  = (const float*)d_in[8];
  const float* bk  = (const float*)d_in[9];
  const float* Wv  = (const float*)d_in[10];
  const float* bv  = (const float*)d_in[11];
  const float* Pq  = (const float*)d_in[12];
  const float* Wup = (const float*)d_in[13];
  const float* bup = (const float*)d_in[14];
  const float* Wdn = (const float*)d_in[15];
  const float* bdn = (const float*)d_in[16];
  float* out = (float*)d_out;

  float *pCA,*pG,*pCB,*pZ,*pU,*ppbv,*pc0;
  bf16 *pA,*pWqt,*pWkt,*pC,*pUe,*pcx,*pPq,*pZe,*pWv,*pCO,*pWu,*pH,*pWd;
  cudaGetSymbolAddress((void**)&pCA,g_CA); cudaGetSymbolAddress((void**)&pG,g_G);
  cudaGetSymbolAddress((void**)&pCB,g_CB); cudaGetSymbolAddress((void**)&pZ,g_Z);
  cudaGetSymbolAddress((void**)&pU,g_U);   cudaGetSymbolAddress((void**)&ppbv,g_pbv);
  cudaGetSymbolAddress((void**)&pc0,g_c0);
  cudaGetSymbolAddress((void**)&pA,e_A);   cudaGetSymbolAddress((void**)&pWqt,e_Wq);
  cudaGetSymbolAddress((void**)&pWkt,e_Wk);cudaGetSymbolAddress((void**)&pC,e_C);
  cudaGetSymbolAddress((void**)&pUe,e_U);  cudaGetSymbolAddress((void**)&pcx,e_cx);
  cudaGetSymbolAddress((void**)&pPq,e_Pq); cudaGetSymbolAddress((void**)&pZe,e_Z);
  cudaGetSymbolAddress((void**)&pWv,e_Wv); cudaGetSymbolAddress((void**)&pCO,e_CO);
  cudaGetSymbolAddress((void**)&pWu,e_Wu); cudaGetSymbolAddress((void**)&pH,e_H);
  cudaGetSymbolAddress((void**)&pWd,e_Wd);

  cudaFuncSetAttribute(lg_k<128,0>, cudaFuncAttributeMaxDynamicSharedMemorySize, SM128B);
  cudaFuncSetAttribute(lg_k<128,1>, cudaFuncAttributeMaxDynamicSharedMemorySize, SM128B);
  cudaFuncSetAttribute(lg_k<128,3>, cudaFuncAttributeMaxDynamicSharedMemorySize, SM128B);
  cudaFuncSetAttribute(lg_k<128,4>, cudaFuncAttributeMaxDynamicSharedMemorySize, SM128B);
  cudaFuncSetAttribute(lg_k<128,5>, cudaFuncAttributeMaxDynamicSharedMemorySize, SM128B);
  cudaFuncSetAttribute(lg_k<64,0>,  cudaFuncAttributeMaxDynamicSharedMemorySize, SM64B);
  cudaFuncSetAttribute(token_k, cudaFuncAttributeMaxDynamicSharedMemorySize, 65536);

  prep_k<<<36,256>>>(Pq, Wv, Wk, Wq, bq, bk, bv, pU, ppbv, pc0);
  convT_k<true ><<<dim3(32,32),256>>>(Wq, pWqt);
  convT_k<false><<<dim3(32,32),256>>>(Wk, pWkt);
  // C = Wq^T Wk -> Bext
  lg_k<128,1><<<dim3(8,8),256,SM128B>>>(pWqt, pWkt, 3072, DIM, DIM, nullptr, pC, nullptr, nullptr);
  conv_k<true ><<<MA, 256>>>(A, pA, DIM, (long)MA*DIM/4);
  // CA = A @ C^T (fp32)
  lg_k<128,0><<<dim3(8,256),256,SM128B>>>(pA, pC, 3072, DIM, DIM, pCA, nullptr, nullptr, nullptr);
  conv_k<false><<<34, 256>>>(pU, pUe, DIM, (long)NU*DIM/4);
  // G = A @ U'^T (fp32, N=34)
  lg_k<64,0><<<dim3(1,256),256,SM64B>>>(pA, pUe, 3072, NU, NU, pG, nullptr, nullptr, nullptr);
  conv_k<true ><<<TOK, 256>>>(ctx, pcx, DIM, (long)TOK*DIM/4);
  conv_k<false><<<32, 256>>>(Pq, pPq, DIM, (long)32*DIM/4);
  // CB = ctx @ Pq^T (fp32, N=32)
  lg_k<64,0><<<dim3(1,32),256,SM64B>>>(pcx, pPq, 3072, 32, 32, pCB, nullptr, nullptr, nullptr);
  token_k<<<TOK,256,65536>>>(A, pCA, pG, pCB, tkw, ppbv, pc0, pZ);
  conv_k<true ><<<TOK, 256>>>(pZ, pZe, DIM, (long)TOK*DIM/4);
  conv_k<false><<<DIM, 256>>>(Wv, pWv, DIM, (long)DIM*DIM/4);
  // CO = Z @ Wv^T + bv + x -> Aext
  lg_k<128,3><<<dim3(8,32),256,SM128B>>>(pZe, pWv, 3072, DIM, DIM, nullptr, pCO, bv, x);
  conv_k<false><<<FDIM, 256>>>(Wup, pWu, DIM, (long)FDIM*DIM/4);
  // H = gelu(CO @ Wup^T + bup) -> Aext
  lg_k<128,4><<<dim3(32,32),256,SM128B>>>(pCO, pWu, 3072, FDIM, FDIM, nullptr, pH, bup, nullptr);
  conv_k<false><<<DIM*4, 256>>>(Wdn, pWd, FDIM, (long)DIM*FDIM/4);
  // out = H @ Wdn^T + bdn (fp32)
  lg_k<128,5><<<dim3(8,32),256,SM128B>>>(pH, pWd, 12288, DIM, DIM, out, nullptr, bdn, nullptr);
}

// round 7
// speedup vs baseline: 1.1327x; 1.0994x over previous
#include <cuda_runtime.h>
#include <cuda_bf16.h>
#include <cstdint>
#include <math.h>
#define DIM 1024
#define TOK 4096
#define MA 32768
#define NU 34
#define FDIM 4096
#define SCL 0.03125f
typedef __nv_bfloat16 bf16;

__device__ float g_CA[(size_t)MA*DIM];
__device__ float g_G [(size_t)MA*NU];
__device__ float g_CB[(size_t)TOK*32];
__device__ float g_Z [(size_t)TOK*DIM];
__device__ float g_U [(size_t)NU*DIM];
__device__ float g_pbv[32], g_c0[1];
__device__ __align__(256) bf16 e_A [(size_t)MA*3*DIM];
__device__ __align__(256) bf16 e_Wq[(size_t)DIM*3*DIM];
__device__ __align__(256) bf16 e_Wk[(size_t)DIM*3*DIM];
__device__ __align__(256) bf16 e_C [(size_t)DIM*3*DIM];
__device__ __align__(256) bf16 e_U [(size_t)NU*3*DIM];
__device__ __align__(256) bf16 e_cx[(size_t)TOK*3*DIM];
__device__ __align__(256) bf16 e_Pq[(size_t)32*3*DIM];
__device__ __align__(256) bf16 e_Z [(size_t)TOK*3*DIM];
__device__ __align__(256) bf16 e_Wv[(size_t)DIM*3*DIM];
__device__ __align__(256) bf16 e_CO[(size_t)TOK*3*DIM];
__device__ __align__(256) bf16 e_Wu[(size_t)FDIM*3*DIM];
__device__ __align__(256) bf16 e_H [(size_t)TOK*3*FDIM];
__device__ __align__(256) bf16 e_Wd[(size_t)DIM*3*FDIM];

__device__ __forceinline__ uint32_t smem_u32(const void* p){
  uint32_t a;
  asm("{ .reg .u64 t; cvta.to.shared.u64 t, %1; cvt.u32.u64 %0, t; }" : "=r"(a) : "l"(p));
  return a;
}
__device__ __forceinline__ void cpa16(uint32_t s, const void* g){
  asm volatile("cp.async.cg.shared.global [%0], [%1], 16;\n" :: "r"(s), "l"(g));
}
__device__ __forceinline__ void mma_bf16(float c[4], const uint32_t a[4], const uint32_t b[2]){
  asm volatile(
    "mma.sync.aligned.m16n8k16.row.col.f32.bf16.bf16.f32 "
    "{%0,%1,%2,%3}, {%4,%5,%6,%7}, {%8,%9}, {%0,%1,%2,%3};\n"
    : "+f"(c[0]), "+f"(c[1]), "+f"(c[2]), "+f"(c[3])
    : "r"(a[0]), "r"(a[1]), "r"(a[2]), "r"(a[3]), "r"(b[0]), "r"(b[1]));
}
#define LDSM4(r, a) \
  asm volatile("ldmatrix.sync.aligned.m8n8.x4.shared.b16 {%0,%1,%2,%3}, [%4];" \
    : "=r"((r)[0]),"=r"((r)[1]),"=r"((r)[2]),"=r"((r)[3]) : "r"(a))
__device__ __forceinline__ void bsp(float v, bf16 &h, bf16 &l){
  h = __float2bfloat16_rn(v); l = __float2bfloat16_rn(v - __bfloat162float(h));
}

// EPI: 0 fp32 | 1 Bext(h,h,l) | 3 +bias+X2->Aext | 4 gelu(+bias)->Aext | 5 +bias->fp32
template<int EPI>
__device__ __forceinline__ void emit(float v, int m, int col, int N,
                                     float* Cf, bf16* Ce,
                                     const float* bias, const float* X2){
  if (EPI==3) v += bias[col] + X2[(size_t)m*N + col];
  if (EPI==4){ v += bias[col]; v = 0.5f*v*(1.0f + erff(v*0.70710678f)); }
  if (EPI==5){ Cf[(size_t)m*N + col] = v + bias[col]; return; }
  if (EPI==0){ Cf[(size_t)m*N + col] = v; return; }
  bf16 h, l; bsp(v, h, l);
  size_t b = (size_t)m*3*N;
  Ce[b + col] = h;
  Ce[b + N + col]   = (EPI==1) ? h : l;
  Ce[b + 2*N + col] = (EPI==1) ? l : h;
}

// C[m,n] = sum_k A[m,k]*B[n,k]; bf16 K-major ext operands. M%128==0, K%64==0.
// 3-stage cp.async pipeline, ldmatrix fragments, 144B rows (conflict-free).
template<int BN, int EPI>
__global__ __launch_bounds__(256,2)
void lg_k(const bf16* __restrict__ A, const bf16* __restrict__ B,
          int K, int N, int Nb,
          float* __restrict__ Cf, bf16* __restrict__ Ce,
          const float* __restrict__ bias, const float* __restrict__ X2)
{
  constexpr int ROWB  = 144;
  constexpr int ATILEB= 128*ROWB;
  constexpr int STAGEB= (128+BN)*ROWB;
  constexpr int CHT   = (128+BN)*8/256;
  constexpr int WN    = BN/2;
  constexpr int NT2   = WN/16;
  extern __shared__ __align__(16) char smraw[];
  const int tid = threadIdx.x;
  const int mBase = blockIdx.y*128, nBase = blockIdx.x*BN;
  const uint32_t smu = smem_u32(smraw);
  const int nK = K/64;

  uint32_t choff[CHT]; const bf16* gp[CHT]; bool val[CHT];
#pragma unroll
  for (int i=0;i<CHT;i++){
    const int c = tid + i*256;
    const int row = c>>3, kc = c&7;
    const bool isA = row < 128;
    const int lrow = isA ? row : row-128;
    choff[i] = (isA ? 0 : ATILEB) + lrow*ROWB + kc*16;
    const int gr = isA ? (mBase+row) : (nBase+lrow);
    gp[i] = (isA ? A : B) + (size_t)gr*K + kc*8;
    val[i] = isA || (nBase+lrow) < Nb;
    if (!val[i]){
      uint4 z = {0u,0u,0u,0u};
#pragma unroll
      for (int st=0; st<3; st++) *(uint4*)(smraw + st*STAGEB + choff[i]) = z;
    }
  }
  auto loadStage = [&](int st){
    if (st < nK){
      const uint32_t b = smu + (st%3)*STAGEB;
      const int ko = st*64;
#pragma unroll
      for (int i=0;i<CHT;i++) if (val[i]) cpa16(b + choff[i], gp[i] + ko);
    }
    asm volatile("cp.async.commit_group;\n":::"memory");
  };

  float acc[2][WN/8][4];
#pragma unroll
  for (int a=0;a<2;a++)
#pragma unroll
    for (int b=0;b<WN/8;b++)
#pragma unroll
      for (int c=0;c<4;c++) acc[a][b][c]=0.f;

  const int warp = tid>>5, lane = tid&31;
  const int wm = (warp>>1)*32, wn = (warp&1)*WN;
  uint32_t aoff[2], boff[NT2];
#pragma unroll
  for (int mt=0;mt<2;mt++)
    aoff[mt] = (uint32_t)(wm + mt*16 + (lane&7) + ((lane>>3)&1)*8)*ROWB + ((lane>>4)&1)*16;
#pragma unroll
  for (int n2=0;n2<NT2;n2++)
    boff[n2] = ATILEB + (uint32_t)(wn + n2*16 + (lane&7) + ((lane>>4)&1)*8)*ROWB + ((lane>>3)&1)*16;

  loadStage(0); loadStage(1);
  for (int kt=0; kt<nK; ++kt){
    asm volatile("cp.async.wait_group 1;\n":::"memory");
    __syncthreads();
    loadStage(kt+2);
    const uint32_t base = smu + (kt%3)*STAGEB;
#pragma unroll
    for (int ks=0; ks<4; ++ks){
      const uint32_t ko = ks*32;
      uint32_t a[2][4];
#pragma unroll
      for (int mt=0;mt<2;mt++) LDSM4(a[mt], base + aoff[mt] + ko);
#pragma unroll
      for (int n2=0;n2<NT2;n2++){
        uint32_t b[4];
        LDSM4(b, base + boff[n2] + ko);
#pragma unroll
        for (int mt=0;mt<2;mt++){
          mma_bf16(acc[mt][2*n2],   a[mt], b);
          mma_bf16(acc[mt][2*n2+1], a[mt], b+2);
        }
      }
    }
  }

  const int r = lane>>2, c2 = (lane&3)*2;
#pragma unroll
  for (int mt=0;mt<2;mt++){
#pragma unroll
    for (int nt=0; nt<WN/8; nt++){
      const int row = mBase + wm + mt*16 + r;
      const int col = nBase + wn + nt*8 + c2;
      if (col < N){
        emit<EPI>(acc[mt][nt][0], row, col, N, Cf, Ce, bias, X2);
        emit<EPI>(acc[mt][nt][2], row+8, col, N, Cf, Ce, bias, X2);
      }
      if (col+1 < N){
        emit<EPI>(acc[mt][nt][1], row, col+1, N, Cf, Ce, bias, X2);
        emit<EPI>(acc[mt][nt][3], row+8, col+1, N, Cf, Ce, bias, X2);
      }
    }
  }
}

// fp32 [R,C] -> ext (A-side h,l,h / B-side h,h,l), row stride 3C
template<bool ASIDE>
__global__ __launch_bounds__(256)
void conv_k(const float* __restrict__ S, bf16* __restrict__ E, int C, long n4){
  long i = (long)blockIdx.x*256 + threadIdx.x;
  if (i >= n4) return;
  int c4 = C/4;
  int r = (int)(i / c4), cc = (int)(i % c4) * 4;
  float4 v = ((const float4*)S)[i];
  float vv[4] = {v.x, v.y, v.z, v.w};
  bf16 h[4], l[4];
#pragma unroll
  for (int u=0;u<4;u++) bsp(vv[u], h[u], l[u]);
  uint2 ph = *(uint2*)h, pl = *(uint2*)l;
  size_t b = (size_t)r*3*C + cc;
  *(uint2*)(E + b)       = ph;
  *(uint2*)(E + b + C)   = ASIDE ? pl : ph;
  *(uint2*)(E + b + 2*C) = ASIDE ? ph : pl;
}
// ext of S^T for S [DIM,DIM]
template<bool ASIDE>
__global__ __launch_bounds__(256)
void convT_k(const float* __restrict__ S, bf16* __restrict__ E){
  __shared__ float t[32][33];
  const int bx = blockIdx.x*32, by = blockIdx.y*32;
  const int tx = threadIdx.x&31, ty = threadIdx.x>>5;
  for (int r=0;r<32;r+=8) t[ty+r][tx] = S[(size_t)(by+ty+r)*DIM + bx+tx];
  __syncthreads();
  for (int r=0;r<32;r+=8){
    float v = t[ty+r][tx];
    bf16 h, l; bsp(v, h, l);
    size_t b = (size_t)(bx+tx)*3*DIM + (by+ty+r);
    E[b] = h;
    E[b + DIM]   = ASIDE ? l : h;
    E[b + 2*DIM] = ASIDE ? h : l;
  }
}

__global__ __launch_bounds__(256)
void prep_k(const float* __restrict__ Pq, const float* __restrict__ Wv,
            const float* __restrict__ Wk, const float* __restrict__ Wq,
            const float* __restrict__ bq, const float* __restrict__ bk,
            const float* __restrict__ bv,
            float* __restrict__ U, float* __restrict__ pbv, float* __restrict__ c0)
{
  __shared__ float srow[DIM];
  int b = blockIdx.x, tid = threadIdx.x;
  if (b < 34){
    const float* src = (b<32) ? Pq + b*DIM : ((b==32) ? bq : bk);
    const float* W   = (b<32) ? Wv : ((b==32) ? Wk : Wq);
    for (int e=tid;e<DIM;e+=256) srow[e]=src[e];
    __syncthreads();
    for (int d=tid; d<DIM; d+=256){
      float acc=0.f;
      for (int e=0;e<DIM;e++) acc += srow[e]*W[(size_t)e*DIM+d];
      U[(size_t)b*DIM+d]=acc;
    }
  } else if (b==34){
    int w = tid>>5, l = tid&31;
    for (int p=w; p<32; p+=8){
      float acc=0.f;
      for (int d=l; d<DIM; d+=32) acc += Pq[p*DIM+d]*bv[d];
      for (int o=16;o;o>>=1) acc += __shfl_down_sync(0xffffffffu, acc, o);
      if (l==0) pbv[p]=acc;
    }
  } else {
    __shared__ float red[256];
    float acc=0.f;
    for (int d=tid; d<DIM; d+=256) acc += bq[d]*bk[d];
    red[tid]=acc; __syncthreads();
    for (int s=128; s>0; s>>=1){ if (tid<s) red[tid]+=red[tid+s]; __syncthreads(); }
    if (tid==0) c0[0]=red[0];
  }
}

__global__ __launch_bounds__(256)
void token_k(const float* __restrict__ A, const float* __restrict__ CA,
             const float* __restrict__ GA, const float* __restrict__ CB,
             const float* __restrict__ tkw, const float* __restrict__ pbv,
             const float* __restrict__ c0p, float* __restrict__ Z)
{
  extern __shared__ __align__(16) char smraw[];
  float* sA = (float*)smraw; float* sC = sA + 8192;
  __shared__ float sGA[8][NU];
  __shared__ float sS[64], sAttn[64], sNps[32][8], sFa[8], sW[8], sScore[32];
  const int t = blockIdx.x, tid = threadIdx.x;
  const size_t base = (size_t)t*8*DIM;
  const float4* A4 = (const float4*)(A + base);
  const float4* C4 = (const float4*)(CA + base);
  float4* sA4 = (float4*)sA; float4* sC4 = (float4*)sC;
  for (int i=tid; i<2048; i+=256){ sA4[i]=A4[i]; sC4[i]=C4[i]; }
  for (int i=tid; i<8*NU; i+=256) sGA[i/NU][i%NU] = GA[(size_t)(t*8 + i/NU)*NU + i%NU];
  __syncthreads();
  int warp = tid>>5, lane = tid&31;
  for (int p8=0;p8<8;p8++){
    int pair = warp*8+p8;
    const float* ai = sA + (pair>>3)*DIM;
    const float* cj = sC + (pair&7)*DIM;
    float acc=0.f;
    for (int d=lane; d<DIM; d+=32) acc += ai[d]*cj[d];
    for (int o=16;o;o>>=1) acc += __shfl_xor_sync(0xffffffffu, acc, o);
    if (lane==0) sS[pair]=acc;
  }
  __syncthreads();
  float c0 = c0p[0];
  if (warp==0 && lane<8){
    int i=lane;
    float s[8], mx=-1e30f;
    for (int j=0;j<8;j++){ s[j]=SCL*(sS[i*8+j]+sGA[j][32]+sGA[i][33]+c0); mx=fmaxf(mx,s[j]); }
    float sum=0.f;
    for (int j=0;j<8;j++){ s[j]=expf(s[j]-mx); sum+=s[j]; }
    float inv=1.f/sum;
    for (int j=0;j<8;j++) sAttn[i*8+j]=s[j]*inv;
  }
  __syncthreads();
  if (warp==1){
    int p=lane;
    const float* w8 = tkw + (size_t)t*8;
    float nb=0.f;
    for (int i=0;i<8;i++){
      float acc=0.f;
      for (int j=0;j<8;j++) acc += sAttn[i*8+j]*sGA[j][p];
      float nps = SCL*(acc + pbv[p]);
      sNps[p][i]=nps; nb += nps * w8[i];
    }
    sScore[p] = 0.5f*nb + 0.5f*CB[(size_t)t*32+p];
  }
  __syncthreads();
  if (tid==0){
    int sel[4]; float sv[4]; unsigned used=0u;
    for (int r2=0;r2<4;r2++){
      float best=-1e30f; int bi=0;
      for (int p=0;p<32;p++) if(!((used>>p)&1u) && sScore[p]>best){best=sScore[p];bi=p;}
      used |= 1u<<bi; sel[r2]=bi; sv[r2]=best;
    }
    float mx=sv[0], tw[4], sum=0.f;
    for(int r2=0;r2<4;r2++){ tw[r2]=expf(sv[r2]-mx); sum+=tw[r2]; }
    float fa[8]={0,0,0,0,0,0,0,0};
    for(int r2=0;r2<4;r2++){
      int p=sel[r2];
      float m2=-1e30f;
      for(int k=0;k<8;k++) m2=fmaxf(m2,sNps[p][k]);
      float e[8], s2=0.f;
      for(int k=0;k<8;k++){ e[k]=expf(sNps[p][k]-m2); s2+=e[k]; }
      float inv=(tw[r2]/sum)/s2;
      for(int k=0;k<8;k++) fa[k]+=e[k]*inv;
    }
    for(int k=0;k<8;k++) sFa[k]=fa[k];
  }
  __syncthreads();
  if (tid<8){
    float w=0.f;
    for(int i=0;i<8;i++) w += sFa[i]*sAttn[i*8+tid];
    sW[tid]=w;
  }
  __syncthreads();
  for (int d=tid; d<DIM; d+=256){
    float acc=0.f;
    for(int j=0;j<8;j++) acc += sW[j]*sA[j*DIM+d];
    Z[(size_t)t*DIM+d]=acc;
  }
}

#define SM3_128 (3*(128+128)*144)
#define SM3_64  (3*(128+64)*144)
extern "C" void kernel_launch(void* const* d_in, const int* in_sizes, int n_in,
                              void* d_out, int out_size) {
  const float* x   = (const float*)d_in[0];
  const float* tkw = (const float*)d_in[3];
  const float* A   = (const float*)d_in[4];
  const float* ctx = (const float*)d_in[5];
  const float* Wq  = (const float*)d_in[6];
  const float* bq  = (const float*)d_in[7];
  const float* Wk  = (const float*)d_in[8];
  const float* bk  = (const float*)d_in[9];
  const float* Wv  = (const float*)d_in[10];
  const float* bv  = (const float*)d_in[11];
  const float* Pq  = (const float*)d_in[12];
  const float* Wup = (const float*)d_in[13];
  const float* bup = (const float*)d_in[14];
  const float* Wdn = (const float*)d_in[15];
  const float* bdn = (const float*)d_in[16];
  float* out = (float*)d_out;

  float *pCA,*pG,*pCB,*pZ,*pU,*ppbv,*pc0;
  bf16 *pA,*pWqt,*pWkt,*pC,*pUe,*pcx,*pPq,*pZe,*pWv,*pCO,*pWu,*pH,*pWd;
  cudaGetSymbolAddress((void**)&pCA,g_CA); cudaGetSymbolAddress((void**)&pG,g_G);
  cudaGetSymbolAddress((void**)&pCB,g_CB); cudaGetSymbolAddress((void**)&pZ,g_Z);
  cudaGetSymbolAddress((void**)&pU,g_U);   cudaGetSymbolAddress((void**)&ppbv,g_pbv);
  cudaGetSymbolAddress((void**)&pc0,g_c0);
  cudaGetSymbolAddress((void**)&pA,e_A);   cudaGetSymbolAddress((void**)&pWqt,e_Wq);
  cudaGetSymbolAddress((void**)&pWkt,e_Wk);cudaGetSymbolAddress((void**)&pC,e_C);
  cudaGetSymbolAddress((void**)&pUe,e_U);  cudaGetSymbolAddress((void**)&pcx,e_cx);
  cudaGetSymbolAddress((void**)&pPq,e_Pq); cudaGetSymbolAddress((void**)&pZe,e_Z);
  cudaGetSymbolAddress((void**)&pWv,e_Wv); cudaGetSymbolAddress((void**)&pCO,e_CO);
  cudaGetSymbolAddress((void**)&pWu,e_Wu); cudaGetSymbolAddress((void**)&pH,e_H);
  cudaGetSymbolAddress((void**)&pWd,e_Wd);

  cudaFuncSetAttribute(lg_k<128,0>, cudaFuncAttributeMaxDynamicSharedMemorySize, SM3_128);
  cudaFuncSetAttribute(lg_k<128,3>, cudaFuncAttributeMaxDynamicSharedMemorySize, SM3_128);
  cudaFuncSetAttribute(lg_k<128,4>, cudaFuncAttributeMaxDynamicSharedMemorySize, SM3_128);
  cudaFuncSetAttribute(lg_k<128,5>, cudaFuncAttributeMaxDynamicSharedMemorySize, SM3_128);
  cudaFuncSetAttribute(lg_k<64,0>,  cudaFuncAttributeMaxDynamicSharedMemorySize, SM3_64);
  cudaFuncSetAttribute(lg_k<64,1>,  cudaFuncAttributeMaxDynamicSharedMemorySize, SM3_64);
  cudaFuncSetAttribute(token_k, cudaFuncAttributeMaxDynamicSharedMemorySize, 65536);

  prep_k<<<36,256>>>(Pq, Wv, Wk, Wq, bq, bk, bv, pU, ppbv, pc0);
  convT_k<true ><<<dim3(32,32),256>>>(Wq, pWqt);
  convT_k<false><<<dim3(32,32),256>>>(Wk, pWkt);
  // C = Wq^T Wk -> Bext
  lg_k<64,1><<<dim3(16,8),256,SM3_64>>>(pWqt, pWkt, 3072, DIM, DIM, nullptr, pC, nullptr, nullptr);
  conv_k<true ><<<MA, 256>>>(A, pA, DIM, (long)MA*DIM/4);
  // CA = A @ C^T (fp32)
  lg_k<128,0><<<dim3(8,256),256,SM3_128>>>(pA, pC, 3072, DIM, DIM, pCA, nullptr, nullptr, nullptr);
  conv_k<false><<<34, 256>>>(pU, pUe, DIM, (long)NU*DIM/4);
  // G = A @ U'^T (fp32, N=34)
  lg_k<64,0><<<dim3(1,256),256,SM3_64>>>(pA, pUe, 3072, NU, NU, pG, nullptr, nullptr, nullptr);
  conv_k<true ><<<TOK, 256>>>(ctx, pcx, DIM, (long)TOK*DIM/4);
  conv_k<false><<<32, 256>>>(Pq, pPq, DIM, (long)32*DIM/4);
  // CB = ctx @ Pq^T (fp32, N=32)
  lg_k<64,0><<<dim3(1,32),256,SM3_64>>>(pcx, pPq, 3072, 32, 32, pCB, nullptr, nullptr, nullptr);
  token_k<<<TOK,256,65536>>>(A, pCA, pG, pCB, tkw, ppbv, pc0, pZ);
  conv_k<true ><<<TOK, 256>>>(pZ, pZe, DIM, (long)TOK*DIM/4);
  conv_k<false><<<DIM, 256>>>(Wv, pWv, DIM, (long)DIM*DIM/4);
  // CO = Z @ Wv^T + bv + x -> Aext
  lg_k<128,3><<<dim3(8,32),256,SM3_128>>>(pZe, pWv, 3072, DIM, DIM, nullptr, pCO, bv, x);
  conv_k<false><<<FDIM, 256>>>(Wup, pWu, DIM, (long)FDIM*DIM/4);
  // H = gelu(CO @ Wup^T + bup) -> Aext
  lg_k<128,4><<<dim3(32,32),256,SM3_128>>>(pCO, pWu, 3072, FDIM, FDIM, nullptr, pH, bup, nullptr);
  conv_k<false><<<DIM*4, 256>>>(Wdn, pWd, FDIM, (long)DIM*FDIM/4);
  // out = H @ Wdn^T + bdn (fp32)
  lg_k<128,5><<<dim3(8,32),256,SM3_128>>>(pH, pWd, 12288, DIM, DIM, out, nullptr, bdn, nullptr);
}